// round 6
// baseline (speedup 1.0000x reference)
#include <cuda_runtime.h>
#include <stdint.h>
#include <stddef.h>

// SNG pipeline, closed form (proven equivalent to the reference scan):
//   sn[b,l] = maj-chain over the anti-diagonal r[b, i, l+i], i = 0..P-1,
//   seeded by a = x_0 & r[b,0,l],  a <- maj(x_i, a, r[b,i,l+i]).
// Fully parallel over (b, l): pure HBM streaming.
//
// THIS ROUND'S EXPERIMENT: output written as float32 (1.0f / 0.0f).
// Five rounds of int writes produced rel_err == 1.000000 exactly, the
// signature of the checker seeing ~0 everywhere (int 1 == float 1.4e-45).
//
// Input decode stays dtype-agnostic: bit = (word != 0) covers int 1 and
// float 1.0f; num decoded via small-int / float-bits discrimination.

__global__ __launch_bounds__(256)
void sng_p8(const unsigned* __restrict__ num,
            const unsigned* __restrict__ r,
            float* __restrict__ out,
            int L, int T)
{
    const int l = blockIdx.x * 256 + threadIdx.x;
    const int b = blockIdx.y;
    if (l >= L) return;

    const unsigned* rb = r + (size_t)b * (8ULL * (size_t)T) + l;

    // Front-batched independent loads for MLP.
    unsigned w0 = __ldg(rb + 0 * T + 0);
    unsigned w1 = __ldg(rb + 1 * T + 1);
    unsigned w2 = __ldg(rb + 2 * T + 2);
    unsigned w3 = __ldg(rb + 3 * T + 3);
    unsigned w4 = __ldg(rb + 4 * T + 4);
    unsigned w5 = __ldg(rb + 5 * T + 5);
    unsigned w6 = __ldg(rb + 6 * T + 6);
    unsigned w7 = __ldg(rb + 7 * T + 7);

    // num decode: 0 -> 0; small raw word -> int32 storage; else float bits.
    unsigned nw = __ldg(num + b);
    int x;
    if (nw == 0u)              x = 0;
    else if (nw < (1u << 24))  x = (int)nw;                      // int32 storage
    else                       x = (int)__uint_as_float(nw);     // float32 storage

    // r bit decode: nonzero word == bit set (covers 1 and 1.0f).
    int r0 = (w0 != 0u), r1 = (w1 != 0u), r2 = (w2 != 0u), r3 = (w3 != 0u);
    int r4 = (w4 != 0u), r5 = (w5 != 0u), r6 = (w6 != 0u), r7 = (w7 != 0u);

    // maj(xi, a, ri) = (a & ri) | (xi & (a | ri)) -> 2 LOP3 per stage.
    int a = (x & 1) & r0;
    int xi;
    xi = (x >> 1) & 1;  a = (a & r1) | (xi & (a | r1));
    xi = (x >> 2) & 1;  a = (a & r2) | (xi & (a | r2));
    xi = (x >> 3) & 1;  a = (a & r3) | (xi & (a | r3));
    xi = (x >> 4) & 1;  a = (a & r4) | (xi & (a | r4));
    xi = (x >> 5) & 1;  a = (a & r5) | (xi & (a | r5));
    xi = (x >> 6) & 1;  a = (a & r6) | (xi & (a | r6));
    xi = (x >> 7) & 1;  a = (a & r7) | (xi & (a | r7));

    out[(size_t)b * (size_t)L + l] = (float)a;   // FLOAT32 output encoding
}

// Generic fallback for any P.
__global__ __launch_bounds__(256)
void sng_generic(const unsigned* __restrict__ num,
                 const unsigned* __restrict__ r,
                 float* __restrict__ out,
                 int P, int L, int T)
{
    const int l = blockIdx.x * 256 + threadIdx.x;
    const int b = blockIdx.y;
    if (l >= L) return;

    unsigned nw = __ldg(num + b);
    int x;
    if (nw == 0u)              x = 0;
    else if (nw < (1u << 24))  x = (int)nw;
    else                       x = (int)__uint_as_float(nw);

    const unsigned* rb = r + (size_t)b * ((size_t)P * (size_t)T) + l;

    unsigned w = __ldg(rb);
    int a = (x & 1) & (w != 0u);
    for (int i = 1; i < P; i++) {
        w = __ldg(rb + (size_t)i * (size_t)T + i);
        int ri = (w != 0u);
        int xi = (x >> i) & 1;
        a = (a & ri) | (xi & (a | ri));
    }
    out[(size_t)b * (size_t)L + l] = (float)a;
}

// Try to solve shapes under a given unit scale: returns true on success.
static bool solve_shapes(const int* in_sizes, int n_in, long long out_elems,
                         long long scale, int i_r,
                         int* o_inum, long long* o_B, long long* o_L, int* o_P)
{
    const long long Sr = (long long)in_sizes[i_r] / scale;
    const long long oe = out_elems / scale;
    if (Sr <= 0 || oe <= 0) return false;
    for (int j = 0; j < n_in; j++) {
        if (j == i_r) continue;
        const long long Bj = (long long)in_sizes[j] / scale;
        if (Bj <= 0 || (oe % Bj) != 0) continue;
        const long long Lj = oe / Bj;
        for (int p = 1; p <= 64; p++) {
            if (Bj * (long long)p * ((long long)p + Lj) == Sr) {
                *o_inum = j; *o_B = Bj; *o_L = Lj; *o_P = p;
                return true;
            }
        }
    }
    return false;
}

extern "C" void kernel_launch(void* const* d_in, const int* in_sizes, int n_in,
                              void* d_out, int out_size)
{
    // r = largest input.
    int i_r = 0;
    for (int i = 1; i < n_in; i++)
        if (in_sizes[i] > in_sizes[i_r]) i_r = i;

    // Solve shapes assuming element counts; fall back to byte units (/4).
    int i_num = -1, P = 8;
    long long B = 0, L = 0;
    if (!solve_shapes(in_sizes, n_in, out_size, 1, i_r, &i_num, &B, &L, &P)) {
        if (!solve_shapes(in_sizes, n_in, out_size, 4, i_r, &i_num, &B, &L, &P)) {
            // Last resort: smallest input is num, assume element counts.
            i_num = (i_r == 0 && n_in > 1) ? 1 : 0;
            for (int i = 0; i < n_in; i++)
                if (i != i_r && in_sizes[i] < in_sizes[i_num]) i_num = i;
            B = in_sizes[i_num];
            L = (B > 0) ? (long long)out_size / B : 1;
            for (int p = 1; p <= 64; p++)
                if (B * (long long)p * ((long long)p + L) == (long long)in_sizes[i_r]) { P = p; break; }
        }
    }
    const int T = (int)(P + L);

    const unsigned* num = (const unsigned*)d_in[i_num];
    const unsigned* r   = (const unsigned*)d_in[i_r];
    float* out          = (float*)d_out;

    dim3 grid((unsigned)((L + 255) / 256), (unsigned)B);
    if (P == 8) {
        sng_p8<<<grid, 256>>>(num, r, out, (int)L, T);
    } else {
        sng_generic<<<grid, 256>>>(num, r, out, P, (int)L, T);
    }
}

// round 7
// speedup vs baseline: 1.0879x; 1.0879x over previous
#include <cuda_runtime.h>
#include <stdint.h>
#include <stddef.h>

// SNG pipeline, closed form: sn[b,l] = maj-chain over anti-diagonal
// r[b, i, l+i], seeded a = x0 & r[b,0,l]. Output dtype: FLOAT32 (confirmed R6).
//
// Fast path: 4 outputs/thread with LDG.128. Bitwise maj over RAW words:
// with masks m_i = -bit_i, the accumulator stays in {0, V} where V is the
// storage's "one" pattern (1 for int32, 0x3F800000 for float32), so no
// per-word decode is needed — one (a != 0) per output at the end.

#define MAJ(a, m, w) (((a) & (w)) | ((m) & ((a) | (w))))

__device__ __forceinline__ int decode_num(unsigned nw) {
    if (nw == 0u)             return 0;
    if (nw < (1u << 24))      return (int)nw;               // int32 storage
    return (int)__uint_as_float(nw);                        // float32 storage
}

__global__ __launch_bounds__(256)
void sng_p8x4(const unsigned* __restrict__ num,
              const unsigned* __restrict__ r,
              float* __restrict__ out,
              int L4, int T)            // L4 = L/4
{
    const int q = blockIdx.x * 256 + threadIdx.x;
    if (q >= L4) return;
    const int l0 = q << 2;
    const int b  = blockIdx.y;

    const unsigned* rb = r + (size_t)b * (8ULL * (size_t)T);

    // Front-batched 128-bit loads (anti-diagonal, statically selected).
    const uint4 A0 = *(const uint4*)(rb + 0 * T + l0);
    const uint4 A1 = *(const uint4*)(rb + 1 * T + l0);
    const uint4 B1 = *(const uint4*)(rb + 1 * T + l0 + 4);
    const uint4 A2 = *(const uint4*)(rb + 2 * T + l0);
    const uint4 B2 = *(const uint4*)(rb + 2 * T + l0 + 4);
    const uint4 A3 = *(const uint4*)(rb + 3 * T + l0);
    const uint4 B3 = *(const uint4*)(rb + 3 * T + l0 + 4);
    const uint4 A4 = *(const uint4*)(rb + 4 * T + l0 + 4);
    const uint4 A5 = *(const uint4*)(rb + 5 * T + l0 + 4);
    const uint4 B5 = *(const uint4*)(rb + 5 * T + l0 + 8);
    const uint4 A6 = *(const uint4*)(rb + 6 * T + l0 + 4);
    const uint4 B6 = *(const uint4*)(rb + 6 * T + l0 + 8);
    const uint4 A7 = *(const uint4*)(rb + 7 * T + l0 + 4);
    const uint4 B7 = *(const uint4*)(rb + 7 * T + l0 + 8);

    const int x = decode_num(__ldg(num + b));
    const unsigned m0 = (unsigned)-( x       & 1);
    const unsigned m1 = (unsigned)-((x >> 1) & 1);
    const unsigned m2 = (unsigned)-((x >> 2) & 1);
    const unsigned m3 = (unsigned)-((x >> 3) & 1);
    const unsigned m4 = (unsigned)-((x >> 4) & 1);
    const unsigned m5 = (unsigned)-((x >> 5) & 1);
    const unsigned m6 = (unsigned)-((x >> 6) & 1);
    const unsigned m7 = (unsigned)-((x >> 7) & 1);

    // Row-i element for output j: (i & 3) + j into the dual-chunk window.
    // row1: A1.y A1.z A1.w B1.x   row2: A2.z A2.w B2.x B2.y
    // row3: A3.w B3.x B3.y B3.z   row5..7 mirror with +4 base.
    unsigned a, acc0, acc1, acc2, acc3;

    a = m0 & A0.x;
    a = MAJ(a, m1, A1.y);  a = MAJ(a, m2, A2.z);  a = MAJ(a, m3, A3.w);
    a = MAJ(a, m4, A4.x);  a = MAJ(a, m5, A5.y);  a = MAJ(a, m6, A6.z);
    a = MAJ(a, m7, A7.w);
    acc0 = a;

    a = m0 & A0.y;
    a = MAJ(a, m1, A1.z);  a = MAJ(a, m2, A2.w);  a = MAJ(a, m3, B3.x);
    a = MAJ(a, m4, A4.y);  a = MAJ(a, m5, A5.z);  a = MAJ(a, m6, A6.w);
    a = MAJ(a, m7, B7.x);
    acc1 = a;

    a = m0 & A0.z;
    a = MAJ(a, m1, A1.w);  a = MAJ(a, m2, B2.x);  a = MAJ(a, m3, B3.y);
    a = MAJ(a, m4, A4.z);  a = MAJ(a, m5, A5.w);  a = MAJ(a, m6, B6.x);
    a = MAJ(a, m7, B7.y);
    acc2 = a;

    a = m0 & A0.w;
    a = MAJ(a, m1, B1.x);  a = MAJ(a, m2, B2.y);  a = MAJ(a, m3, B3.z);
    a = MAJ(a, m4, A4.w);  a = MAJ(a, m5, B5.x);  a = MAJ(a, m6, B6.y);
    a = MAJ(a, m7, B7.z);
    acc3 = a;

    float4 o;
    o.x = acc0 ? 1.0f : 0.0f;
    o.y = acc1 ? 1.0f : 0.0f;
    o.z = acc2 ? 1.0f : 0.0f;
    o.w = acc3 ? 1.0f : 0.0f;
    *(float4*)(out + (size_t)b * ((size_t)L4 << 2) + l0) = o;
}

// Scalar P==8 path (verified in R6) for shapes where the x4 path can't run.
__global__ __launch_bounds__(256)
void sng_p8(const unsigned* __restrict__ num,
            const unsigned* __restrict__ r,
            float* __restrict__ out,
            int L, int T)
{
    const int l = blockIdx.x * 256 + threadIdx.x;
    const int b = blockIdx.y;
    if (l >= L) return;

    const unsigned* rb = r + (size_t)b * (8ULL * (size_t)T) + l;
    unsigned w0 = __ldg(rb + 0 * T + 0), w1 = __ldg(rb + 1 * T + 1);
    unsigned w2 = __ldg(rb + 2 * T + 2), w3 = __ldg(rb + 3 * T + 3);
    unsigned w4 = __ldg(rb + 4 * T + 4), w5 = __ldg(rb + 5 * T + 5);
    unsigned w6 = __ldg(rb + 6 * T + 6), w7 = __ldg(rb + 7 * T + 7);

    const int x = decode_num(__ldg(num + b));
    unsigned a = ((unsigned)-(x & 1)) & w0;
    a = MAJ(a, (unsigned)-((x >> 1) & 1), w1);
    a = MAJ(a, (unsigned)-((x >> 2) & 1), w2);
    a = MAJ(a, (unsigned)-((x >> 3) & 1), w3);
    a = MAJ(a, (unsigned)-((x >> 4) & 1), w4);
    a = MAJ(a, (unsigned)-((x >> 5) & 1), w5);
    a = MAJ(a, (unsigned)-((x >> 6) & 1), w6);
    a = MAJ(a, (unsigned)-((x >> 7) & 1), w7);
    out[(size_t)b * (size_t)L + l] = a ? 1.0f : 0.0f;
}

// Generic fallback for any P.
__global__ __launch_bounds__(256)
void sng_generic(const unsigned* __restrict__ num,
                 const unsigned* __restrict__ r,
                 float* __restrict__ out,
                 int P, int L, int T)
{
    const int l = blockIdx.x * 256 + threadIdx.x;
    const int b = blockIdx.y;
    if (l >= L) return;

    const int x = decode_num(__ldg(num + b));
    const unsigned* rb = r + (size_t)b * ((size_t)P * (size_t)T) + l;

    unsigned a = ((unsigned)-(x & 1)) & __ldg(rb);
    for (int i = 1; i < P; i++) {
        unsigned w = __ldg(rb + (size_t)i * (size_t)T + i);
        unsigned m = (unsigned)-((x >> i) & 1);
        a = MAJ(a, m, w);
    }
    out[(size_t)b * (size_t)L + l] = a ? 1.0f : 0.0f;
}

static bool solve_shapes(const int* in_sizes, int n_in, long long out_elems,
                         long long scale, int i_r,
                         int* o_inum, long long* o_B, long long* o_L, int* o_P)
{
    const long long Sr = (long long)in_sizes[i_r] / scale;
    const long long oe = out_elems / scale;
    if (Sr <= 0 || oe <= 0) return false;
    for (int j = 0; j < n_in; j++) {
        if (j == i_r) continue;
        const long long Bj = (long long)in_sizes[j] / scale;
        if (Bj <= 0 || (oe % Bj) != 0) continue;
        const long long Lj = oe / Bj;
        for (int p = 1; p <= 64; p++) {
            if (Bj * (long long)p * ((long long)p + Lj) == Sr) {
                *o_inum = j; *o_B = Bj; *o_L = Lj; *o_P = p;
                return true;
            }
        }
    }
    return false;
}

extern "C" void kernel_launch(void* const* d_in, const int* in_sizes, int n_in,
                              void* d_out, int out_size)
{
    int i_r = 0;
    for (int i = 1; i < n_in; i++)
        if (in_sizes[i] > in_sizes[i_r]) i_r = i;

    int i_num = -1, P = 8;
    long long B = 0, L = 0;
    if (!solve_shapes(in_sizes, n_in, out_size, 1, i_r, &i_num, &B, &L, &P) &&
        !solve_shapes(in_sizes, n_in, out_size, 4, i_r, &i_num, &B, &L, &P)) {
        i_num = (i_r == 0 && n_in > 1) ? 1 : 0;
        for (int i = 0; i < n_in; i++)
            if (i != i_r && in_sizes[i] < in_sizes[i_num]) i_num = i;
        B = in_sizes[i_num];
        L = (B > 0) ? (long long)out_size / B : 1;
        for (int p = 1; p <= 64; p++)
            if (B * (long long)p * ((long long)p + L) == (long long)in_sizes[i_r]) { P = p; break; }
    }
    const int T = (int)(P + L);

    const unsigned* num = (const unsigned*)d_in[i_num];
    const unsigned* r   = (const unsigned*)d_in[i_r];
    float* out          = (float*)d_out;

    // Fast x4 path needs P==8, L%4==0, T%4==0 (16B-aligned rows), and
    // headroom: row i max touched index l0+(i&~3)+7 <= T-1 holds since
    // l0 <= L-4 and (i&~3)+7 <= 11 <= P+3.
    if (P == 8 && (L & 3) == 0 && (T & 3) == 0) {
        const int L4 = (int)(L >> 2);
        dim3 grid((unsigned)((L4 + 255) / 256), (unsigned)B);
        sng_p8x4<<<grid, 256>>>(num, r, out, L4, T);
    } else if (P == 8) {
        dim3 grid((unsigned)((L + 255) / 256), (unsigned)B);
        sng_p8<<<grid, 256>>>(num, r, out, (int)L, T);
    } else {
        dim3 grid((unsigned)((L + 255) / 256), (unsigned)B);
        sng_generic<<<grid, 256>>>(num, r, out, P, (int)L, T);
    }
}